// round 5
// baseline (speedup 1.0000x reference)
#include <cuda_runtime.h>
#include <math.h>

// ---------------------------------------------------------------------------
// Problem constants
// ---------------------------------------------------------------------------
#define BATCH      8
#define STRIDE_F   32.0f
#define N_CELLS    196         // 14*14
#define WS_GRID    14
#define NUM_CLS    20
#define HEAD_OUT   25          // 1 + 20 + 4
#define CONF_TH    0.01f
#define NMS_TH     0.5f

// ---------------------------------------------------------------------------
// Scratch buffers (static __device__ arrays: allocation-free, capture-safe).
// Ping-pong aliasing: activations alternate between A and B; safe because all
// kernels run sequentially on the default stream.
//   A holds h1 (102.8 MB), then h3 (25.7 MB), then h5 (3.2 MB)
//   B holds h2 ( 51.4 MB), then h4 (12.8 MB)
// ---------------------------------------------------------------------------
__device__ float g_bufA[8L * 64 * 224 * 224];    // 102.8 MB
__device__ float g_bufB[8L * 128 * 112 * 112];   //  51.4 MB
__device__ float g_pred [8 * HEAD_OUT * N_CELLS];
__device__ float g_boxes[8 * N_CELLS * 4];
__device__ float g_cls  [8 * N_CELLS * NUM_CLS];

// ---------------------------------------------------------------------------
// 3x3 stride-2 conv + ReLU, SAME padding (JAX: pad_lo=0, pad_hi=1).
// Tile: 64 output channels x (8 rows x 16 cols) pixels per block, 256 threads.
// Each thread: 4 channels x 8 pixels (32 accumulators).
// Input tile stored de-interleaved (even/odd columns) in smem so the stride-2
// column access pattern becomes unit-stride -> conflict-free LDS.
// ---------------------------------------------------------------------------
template<int CIN, int COUT, int HIN, int WIN>
__global__ __launch_bounds__(256)
void conv3x3s2_relu(const float* __restrict__ in,
                    const float* __restrict__ w,
                    float* __restrict__ out)
{
    constexpr int HOUT = HIN / 2;
    constexpr int WOUT = WIN / 2;
    constexpr int CHUNK = (CIN % 8 == 0) ? 8 : CIN;   // 8, or 3 for layer 1
    constexpr int NTX = (WOUT + 15) / 16;

    const int bx  = blockIdx.x % NTX;
    const int by  = blockIdx.x / NTX;
    const int ox0 = bx * 16;
    const int oy0 = by * 8;
    const int co0 = blockIdx.y * 64;
    const int b   = blockIdx.z;

    __shared__ float s_even[CHUNK][17][17];  // even input cols (lx = 0,2,...,32)
    __shared__ float s_odd [CHUNK][17][16];  // odd  input cols (lx = 1,3,...,31)
    __shared__ float s_w[64][CHUNK][9];

    const int tid = threadIdx.x;
    const int tc  = tid >> 4;    // 0..15  -> channels tc*4 .. tc*4+3
    const int tp  = tid & 15;    // 0..15  -> output column within tile

    float acc[4][8];
#pragma unroll
    for (int j = 0; j < 4; j++)
#pragma unroll
        for (int r = 0; r < 8; r++) acc[j][r] = 0.0f;

    const float* in_b = in + (size_t)b * CIN * HIN * WIN;

    for (int ci0 = 0; ci0 < CIN; ci0 += CHUNK) {
        __syncthreads();   // protect smem from previous iteration's readers

        // ---- load input tile: CHUNK channels x 17 rows x 33 cols ----
        for (int idx = tid; idx < CHUNK * 17 * 33; idx += 256) {
            int cc  = idx / (17 * 33);
            int rem = idx - cc * (17 * 33);
            int ly  = rem / 33;
            int lx  = rem - ly * 33;
            int iy  = 2 * oy0 + ly;        // pad_lo = 0: never negative
            int ix  = 2 * ox0 + lx;
            float v = 0.0f;
            if (iy < HIN && ix < WIN)
                v = in_b[((size_t)(ci0 + cc) * HIN + iy) * WIN + ix];
            if (lx & 1) s_odd [cc][ly][lx >> 1] = v;
            else        s_even[cc][ly][lx >> 1] = v;
        }

        // ---- load weight chunk: 64 x CHUNK x 9 (contiguous per co) ----
        for (int idx = tid; idx < 64 * CHUNK * 9; idx += 256) {
            int co  = idx / (CHUNK * 9);
            int rem = idx - co * (CHUNK * 9);
            s_w[co][rem / 9][rem % 9] = w[(size_t)(co0 + co) * CIN * 9 + ci0 * 9 + rem];
        }
        __syncthreads();

        // ---- compute ----
        for (int cc = 0; cc < CHUNK; cc++) {
#pragma unroll
            for (int ky = 0; ky < 3; ky++) {
#pragma unroll
                for (int kx = 0; kx < 3; kx++) {
                    float wv[4];
#pragma unroll
                    for (int j = 0; j < 4; j++)
                        wv[j] = s_w[tc * 4 + j][cc][ky * 3 + kx];
                    float iv[8];
#pragma unroll
                    for (int r = 0; r < 8; r++) {
                        int ly = 2 * r + ky;
                        iv[r] = (kx == 1) ? s_odd[cc][ly][tp]
                                          : s_even[cc][ly][tp + (kx >> 1)];
                    }
#pragma unroll
                    for (int j = 0; j < 4; j++)
#pragma unroll
                        for (int r = 0; r < 8; r++)
                            acc[j][r] = fmaf(wv[j], iv[r], acc[j][r]);
                }
            }
        }
    }

    // ---- epilogue: ReLU + store ----
    float* out_b = out + (size_t)b * COUT * HOUT * WOUT;
    const int ox = ox0 + tp;
    if (ox < WOUT) {
#pragma unroll
        for (int j = 0; j < 4; j++) {
            int co = co0 + tc * 4 + j;
#pragma unroll
            for (int r = 0; r < 8; r++) {
                int oy = oy0 + r;
                if (oy < HOUT)
                    out_b[((size_t)co * HOUT + oy) * WOUT + ox] = fmaxf(acc[j][r], 0.0f);
            }
        }
    }
}

// ---------------------------------------------------------------------------
// 1x1 head conv: pred[b][o][p] = sum_ci h5[b][ci][p] * w[o][ci]
// ---------------------------------------------------------------------------
__global__ void yolo_head_kernel(const float* __restrict__ h5,
                                 const float* __restrict__ w,
                                 float* __restrict__ pred)
{
    const int b = blockIdx.x;
    const int o = blockIdx.y;
    const int p = threadIdx.x;
    if (p >= N_CELLS) return;
    const float* hb = h5 + (size_t)b * 512 * N_CELLS;
    const float* wo = w + o * 512;
    float s = 0.0f;
#pragma unroll 8
    for (int ci = 0; ci < 512; ci++)
        s = fmaf(hb[ci * N_CELLS + p], wo[ci], s);
    pred[(b * HEAD_OUT + o) * N_CELLS + p] = s;
}

// ---------------------------------------------------------------------------
// Decode: sigmoid conf, softmax*conf class scores, box decode + clip.
// Writes boxes to d_out[...,:4] and scratch buffers for NMS.
// ---------------------------------------------------------------------------
__global__ void yolo_decode_kernel(const float* __restrict__ pred,
                                   float* __restrict__ boxes,
                                   float* __restrict__ cls,
                                   float* __restrict__ out)
{
    const int b = blockIdx.x;
    const int p = threadIdx.x;
    if (p >= N_CELLS) return;
    const float* pb = pred + (size_t)b * HEAD_OUT * N_CELLS;

    float conf = 1.0f / (1.0f + expf(-pb[p]));

    float v[NUM_CLS];
    float m = -1e30f;
#pragma unroll
    for (int c = 0; c < NUM_CLS; c++) {
        v[c] = pb[(1 + c) * N_CELLS + p];
        m = fmaxf(m, v[c]);
    }
    float s = 0.0f;
#pragma unroll
    for (int c = 0; c < NUM_CLS; c++) { v[c] = expf(v[c] - m); s += v[c]; }
    float inv = conf / s;

    float tx = pb[21 * N_CELLS + p];
    float ty = pb[22 * N_CELLS + p];
    float tw = pb[23 * N_CELLS + p];
    float th = pb[24 * N_CELLS + p];

    float gx = (float)(p % WS_GRID);
    float gy = (float)(p / WS_GRID);
    float cx = (1.0f / (1.0f + expf(-tx)) + gx) * STRIDE_F;
    float cy = (1.0f / (1.0f + expf(-ty)) + gy) * STRIDE_F;
    float bw = expf(tw) * STRIDE_F;
    float bh = expf(th) * STRIDE_F;

    float x1 = (cx - bw * 0.5f) / 448.0f;
    float y1 = (cy - bh * 0.5f) / 448.0f;
    float x2 = (cx + bw * 0.5f) / 448.0f;
    float y2 = (cy + bh * 0.5f) / 448.0f;
    x1 = fminf(fmaxf(x1, 0.0f), 1.0f);
    y1 = fminf(fmaxf(y1, 0.0f), 1.0f);
    x2 = fminf(fmaxf(x2, 0.0f), 1.0f);
    y2 = fminf(fmaxf(y2, 0.0f), 1.0f);

    const int row = b * N_CELLS + p;
    boxes[row * 4 + 0] = x1;
    boxes[row * 4 + 1] = y1;
    boxes[row * 4 + 2] = x2;
    boxes[row * 4 + 3] = y2;
    out[row * 24 + 0] = x1;
    out[row * 24 + 1] = y1;
    out[row * 24 + 2] = x2;
    out[row * 24 + 3] = y2;
#pragma unroll
    for (int c = 0; c < NUM_CLS; c++)
        cls[row * NUM_CLS + c] = v[c] * inv;
}

// ---------------------------------------------------------------------------
// Per-(batch, class) greedy NMS. One block per problem.
// Stable descending sort by rank counting (matches jnp.argsort(-s) stable),
// then 196 barrier-stepped suppression iterations (only kept boxes suppress).
// ---------------------------------------------------------------------------
__global__ void yolo_nms_kernel(const float* __restrict__ boxes,
                                const float* __restrict__ cls,
                                float* __restrict__ out)
{
    const int c = blockIdx.x;   // class
    const int b = blockIdx.y;   // batch
    const int t = threadIdx.x;

    __shared__ float ss[N_CELLS];
    __shared__ float sx1[N_CELLS], sy1[N_CELLS], sx2[N_CELLS], sy2[N_CELLS];
    __shared__ float sa[N_CELLS];
    __shared__ int   sorder[N_CELLS];
    __shared__ int   skeep[N_CELLS];

    if (t < N_CELLS) {
        const int row = b * N_CELLS + t;
        ss[t] = cls[row * NUM_CLS + c];
        float x1 = boxes[row * 4 + 0];
        float y1 = boxes[row * 4 + 1];
        float x2 = boxes[row * 4 + 2];
        float y2 = boxes[row * 4 + 3];
        sx1[t] = x1; sy1[t] = y1; sx2[t] = x2; sy2[t] = y2;
        sa[t] = fmaxf(x2 - x1, 0.0f) * fmaxf(y2 - y1, 0.0f);
    }
    __syncthreads();

    // stable descending rank (matches stable argsort of -scores)
    if (t < N_CELLS) {
        float sp = ss[t];
        int r = 0;
        for (int q = 0; q < N_CELLS; q++) {
            float sq = ss[q];
            r += (sq > sp) || (sq == sp && q < t);
        }
        sorder[r] = t;
        skeep[r]  = (sp > CONF_TH) ? 1 : 0;
    }
    __syncthreads();

    // fetch own (sorted-position) box into registers
    int pj = 0;
    float bx1 = 0.f, by1 = 0.f, bx2 = 0.f, by2 = 0.f, ba = 0.f;
    if (t < N_CELLS) {
        pj  = sorder[t];
        bx1 = sx1[pj]; by1 = sy1[pj]; bx2 = sx2[pj]; by2 = sy2[pj]; ba = sa[pj];
    }

    for (int i = 0; i < N_CELLS - 1; i++) {
        if (skeep[i]) {
            int pi = sorder[i];
            float ax1 = sx1[pi], ay1 = sy1[pi];
            float ax2 = sx2[pi], ay2 = sy2[pi];
            float aa  = sa[pi];
            if (t < N_CELLS && t > i && skeep[t]) {
                float ix1 = fmaxf(ax1, bx1), iy1 = fmaxf(ay1, by1);
                float ix2 = fminf(ax2, bx2), iy2 = fminf(ay2, by2);
                float inter = fmaxf(ix2 - ix1, 0.0f) * fmaxf(iy2 - iy1, 0.0f);
                float iou = inter / (aa + ba - inter + 1e-14f);
                if (iou > NMS_TH) skeep[t] = 0;
            }
        }
        __syncthreads();
    }

    if (t < N_CELLS) {
        const int row = b * N_CELLS + pj;
        out[row * 24 + 4 + c] = ss[pj] * (skeep[t] ? 1.0f : 0.0f);
    }
}

// ---------------------------------------------------------------------------
// Launch
// ---------------------------------------------------------------------------
extern "C" void kernel_launch(void* const* d_in, const int* in_sizes, int n_in,
                              void* d_out, int out_size)
{
    const float* x  = (const float*)d_in[0];
    const float* w1 = (const float*)d_in[1];
    const float* w2 = (const float*)d_in[2];
    const float* w3 = (const float*)d_in[3];
    const float* w4 = (const float*)d_in[4];
    const float* w5 = (const float*)d_in[5];
    const float* wh = (const float*)d_in[6];
    float* out = (float*)d_out;

    float *bufA, *bufB, *pred, *boxes, *cls;
    cudaGetSymbolAddress((void**)&bufA, g_bufA);
    cudaGetSymbolAddress((void**)&bufB, g_bufB);
    cudaGetSymbolAddress((void**)&pred, g_pred);
    cudaGetSymbolAddress((void**)&boxes, g_boxes);
    cudaGetSymbolAddress((void**)&cls, g_cls);

    // Ping-pong: h1->A, h2->B, h3->A, h4->B, h5->A (sequential stream => safe)
    float* h1 = bufA;
    float* h2 = bufB;
    float* h3 = bufA;
    float* h4 = bufB;
    float* h5 = bufA;

    {   // L1: 3 -> 64, 448 -> 224
        constexpr int NTX = (224 + 15) / 16, NTY = (224 + 7) / 8;
        conv3x3s2_relu<3, 64, 448, 448><<<dim3(NTX * NTY, 1, BATCH), 256>>>(x, w1, h1);
    }
    {   // L2: 64 -> 128, 224 -> 112
        constexpr int NTX = (112 + 15) / 16, NTY = (112 + 7) / 8;
        conv3x3s2_relu<64, 128, 224, 224><<<dim3(NTX * NTY, 2, BATCH), 256>>>(h1, w2, h2);
    }
    {   // L3: 128 -> 256, 112 -> 56
        constexpr int NTX = (56 + 15) / 16, NTY = (56 + 7) / 8;
        conv3x3s2_relu<128, 256, 112, 112><<<dim3(NTX * NTY, 4, BATCH), 256>>>(h2, w3, h3);
    }
    {   // L4: 256 -> 512, 56 -> 28
        constexpr int NTX = (28 + 15) / 16, NTY = (28 + 7) / 8;
        conv3x3s2_relu<256, 512, 56, 56><<<dim3(NTX * NTY, 8, BATCH), 256>>>(h3, w4, h4);
    }
    {   // L5: 512 -> 512, 28 -> 14
        constexpr int NTX = (14 + 15) / 16, NTY = (14 + 7) / 8;
        conv3x3s2_relu<512, 512, 28, 28><<<dim3(NTX * NTY, 8, BATCH), 256>>>(h4, w5, h5);
    }

    yolo_head_kernel<<<dim3(BATCH, HEAD_OUT), 224>>>(h5, wh, pred);
    yolo_decode_kernel<<<BATCH, 224>>>(pred, boxes, cls, out);
    yolo_nms_kernel<<<dim3(NUM_CLS, BATCH), 224>>>(boxes, cls, out);
}

// round 6
// speedup vs baseline: 1.1508x; 1.1508x over previous
#include <cuda_runtime.h>
#include <math.h>

// ---------------------------------------------------------------------------
// Problem constants
// ---------------------------------------------------------------------------
#define BATCH      8
#define STRIDE_F   32.0f
#define N_CELLS    196         // 14*14
#define WS_GRID    14
#define NUM_CLS    20
#define HEAD_OUT   25          // 1 + 20 + 4
#define CONF_TH    0.01f
#define NMS_TH     0.5f

// ---------------------------------------------------------------------------
// Scratch buffers (static __device__ arrays: allocation-free, capture-safe).
// Ping-pong aliasing (sequential default-stream execution makes this safe):
//   A holds h1 (102.8 MB), then h3 (25.7 MB), then h5 (3.2 MB)
//   B holds h2 ( 51.4 MB), then h4 (12.8 MB)
// ---------------------------------------------------------------------------
__device__ float g_bufA[8L * 64 * 224 * 224];    // 102.8 MB
__device__ float g_bufB[8L * 128 * 112 * 112];   //  51.4 MB
__device__ float g_pred [8 * HEAD_OUT * N_CELLS];
__device__ float g_boxes[8 * N_CELLS * 4];
__device__ float g_cls  [8 * N_CELLS * NUM_CLS];

// ---------------------------------------------------------------------------
// 3x3 stride-2 conv + ReLU, SAME padding (JAX: pad_lo=0, pad_hi=1).
//
// v2 (issue-economy rework):
//  - 128 threads/block, tile = 64 co x (8 rows x 16 cols).
//  - Each thread: 8 co x 8 rows x 1 col = 64 accumulators.
//  - Weights staged in smem co-contiguous ([cc][k][68]) -> 2x LDS.128/kpos.
//  - All inner-loop smem loads are [base + immediate]; bases advance once
//    per input channel (3 IADDs per 666 issues).
//  - Input tile de-interleaved even/odd columns: stride-2 access -> unit
//    stride, conflict-free (per-warp only 16 distinct addresses = broadcast).
// ---------------------------------------------------------------------------
template<int CIN, int COUT, int HIN, int WIN>
__global__ __launch_bounds__(128, 4)
void conv3x3s2_relu(const float* __restrict__ in,
                    const float* __restrict__ w,
                    float* __restrict__ out)
{
    constexpr int HOUT = HIN / 2;
    constexpr int WOUT = WIN / 2;
    constexpr int CHUNK = (CIN % 8 == 0) ? 8 : CIN;   // 8, or 3 for layer 1
    constexpr int NTX = (WOUT + 15) / 16;

    const int bx  = blockIdx.x % NTX;
    const int by  = blockIdx.x / NTX;
    const int ox0 = bx * 16;
    const int oy0 = by * 8;
    const int co0 = blockIdx.y * 64;
    const int b   = blockIdx.z;

    __shared__ float s_even[CHUNK][17][17];              // even input cols
    __shared__ float s_odd [CHUNK][17][16];              // odd  input cols
    __shared__ __align__(16) float s_w[CHUNK][9][68];    // [cc][k][co], pad 68

    const int tid = threadIdx.x;   // 0..127
    const int tc  = tid >> 4;      // 0..7  -> co = co0 + tc*8 .. +7
    const int tp  = tid & 15;      // 0..15 -> output column within tile

    float acc[8][8] = {};

    const float* in_b = in + (size_t)b * CIN * HIN * WIN;
    const float* wg   = w + (size_t)co0 * CIN * 9;

    for (int ci0 = 0; ci0 < CIN; ci0 += CHUNK) {
        __syncthreads();   // protect smem from previous iteration's readers

        // ---- input tile: CHUNK channels x 17 rows x 33 cols ----
        for (int idx = tid; idx < CHUNK * 17 * 33; idx += 128) {
            int cc  = idx / (17 * 33);
            int rem = idx - cc * (17 * 33);
            int ly  = rem / 33;
            int lx  = rem - ly * 33;
            int iy  = 2 * oy0 + ly;        // pad_lo = 0: never negative
            int ix  = 2 * ox0 + lx;
            float v = 0.0f;
            if (iy < HIN && ix < WIN)
                v = in_b[((size_t)(ci0 + cc) * HIN + iy) * WIN + ix];
            if (lx & 1) s_odd [cc][ly][lx >> 1] = v;
            else        s_even[cc][ly][lx >> 1] = v;
        }

        // ---- weights: coalesced global read (72 contiguous per co),
        //      transposed store into [cc*9+k][co] (stride 68 -> 4-way max) ----
        {
            float* swf = &s_w[0][0][0];
            for (int idx = tid; idx < 64 * CHUNK * 9; idx += 128) {
                int co  = idx / (CHUNK * 9);
                int rem = idx - co * (CHUNK * 9);   // rem = cc*9 + k
                swf[rem * 68 + co] = wg[(size_t)co * CIN * 9 + ci0 * 9 + rem];
            }
        }
        __syncthreads();

        // ---- compute: all loads [base + imm]; bases bumped once per cc ----
        const float* pe = &s_even[0][0][0] + tp;
        const float* po = &s_odd [0][0][0] + tp;
        const float* pw = &s_w[0][0][0] + tc * 8;

#pragma unroll 1
        for (int cc = 0; cc < CHUNK; cc++) {
#pragma unroll
            for (int ky = 0; ky < 3; ky++) {
#pragma unroll
                for (int kx = 0; kx < 3; kx++) {
                    const int kp = ky * 3 + kx;
                    float4 wa = *reinterpret_cast<const float4*>(pw + kp * 68);
                    float4 wb = *reinterpret_cast<const float4*>(pw + kp * 68 + 4);
                    float iv[8];
#pragma unroll
                    for (int r = 0; r < 8; r++) {
                        const int ly = 2 * r + ky;
                        iv[r] = (kx == 1) ? po[ly * 16]
                                          : pe[ly * 17 + (kx >> 1)];
                    }
                    const float wv[8] = { wa.x, wa.y, wa.z, wa.w,
                                          wb.x, wb.y, wb.z, wb.w };
#pragma unroll
                    for (int j = 0; j < 8; j++)
#pragma unroll
                        for (int r = 0; r < 8; r++)
                            acc[j][r] = fmaf(wv[j], iv[r], acc[j][r]);
                }
            }
            pe += 17 * 17;   // 289
            po += 17 * 16;   // 272
            pw += 9 * 68;    // 612
        }
    }

    // ---- epilogue: ReLU + store ----
    float* out_b = out + (size_t)b * COUT * HOUT * WOUT;
    const int ox = ox0 + tp;
    if (ox < WOUT) {
#pragma unroll
        for (int j = 0; j < 8; j++) {
            int co = co0 + tc * 8 + j;
#pragma unroll
            for (int r = 0; r < 8; r++) {
                int oy = oy0 + r;
                if (oy < HOUT)
                    out_b[((size_t)co * HOUT + oy) * WOUT + ox] = fmaxf(acc[j][r], 0.0f);
            }
        }
    }
}

// ---------------------------------------------------------------------------
// 1x1 head conv: pred[b][o][p] = sum_ci h5[b][ci][p] * w[o][ci]
// ---------------------------------------------------------------------------
__global__ void yolo_head_kernel(const float* __restrict__ h5,
                                 const float* __restrict__ w,
                                 float* __restrict__ pred)
{
    const int b = blockIdx.x;
    const int o = blockIdx.y;
    const int p = threadIdx.x;
    if (p >= N_CELLS) return;
    const float* hb = h5 + (size_t)b * 512 * N_CELLS;
    const float* wo = w + o * 512;
    float s = 0.0f;
#pragma unroll 8
    for (int ci = 0; ci < 512; ci++)
        s = fmaf(hb[ci * N_CELLS + p], wo[ci], s);
    pred[(b * HEAD_OUT + o) * N_CELLS + p] = s;
}

// ---------------------------------------------------------------------------
// Decode: sigmoid conf, softmax*conf class scores, box decode + clip.
// ---------------------------------------------------------------------------
__global__ void yolo_decode_kernel(const float* __restrict__ pred,
                                   float* __restrict__ boxes,
                                   float* __restrict__ cls,
                                   float* __restrict__ out)
{
    const int b = blockIdx.x;
    const int p = threadIdx.x;
    if (p >= N_CELLS) return;
    const float* pb = pred + (size_t)b * HEAD_OUT * N_CELLS;

    float conf = 1.0f / (1.0f + expf(-pb[p]));

    float v[NUM_CLS];
    float m = -1e30f;
#pragma unroll
    for (int c = 0; c < NUM_CLS; c++) {
        v[c] = pb[(1 + c) * N_CELLS + p];
        m = fmaxf(m, v[c]);
    }
    float s = 0.0f;
#pragma unroll
    for (int c = 0; c < NUM_CLS; c++) { v[c] = expf(v[c] - m); s += v[c]; }
    float inv = conf / s;

    float tx = pb[21 * N_CELLS + p];
    float ty = pb[22 * N_CELLS + p];
    float tw = pb[23 * N_CELLS + p];
    float th = pb[24 * N_CELLS + p];

    float gx = (float)(p % WS_GRID);
    float gy = (float)(p / WS_GRID);
    float cx = (1.0f / (1.0f + expf(-tx)) + gx) * STRIDE_F;
    float cy = (1.0f / (1.0f + expf(-ty)) + gy) * STRIDE_F;
    float bw = expf(tw) * STRIDE_F;
    float bh = expf(th) * STRIDE_F;

    float x1 = (cx - bw * 0.5f) / 448.0f;
    float y1 = (cy - bh * 0.5f) / 448.0f;
    float x2 = (cx + bw * 0.5f) / 448.0f;
    float y2 = (cy + bh * 0.5f) / 448.0f;
    x1 = fminf(fmaxf(x1, 0.0f), 1.0f);
    y1 = fminf(fmaxf(y1, 0.0f), 1.0f);
    x2 = fminf(fmaxf(x2, 0.0f), 1.0f);
    y2 = fminf(fmaxf(y2, 0.0f), 1.0f);

    const int row = b * N_CELLS + p;
    boxes[row * 4 + 0] = x1;
    boxes[row * 4 + 1] = y1;
    boxes[row * 4 + 2] = x2;
    boxes[row * 4 + 3] = y2;
    out[row * 24 + 0] = x1;
    out[row * 24 + 1] = y1;
    out[row * 24 + 2] = x2;
    out[row * 24 + 3] = y2;
#pragma unroll
    for (int c = 0; c < NUM_CLS; c++)
        cls[row * NUM_CLS + c] = v[c] * inv;
}

// ---------------------------------------------------------------------------
// Per-(batch, class) greedy NMS. One block per problem.
// Stable descending sort by rank counting (matches stable argsort of -s),
// then 196 barrier-stepped suppression iterations (kept boxes suppress).
// ---------------------------------------------------------------------------
__global__ void yolo_nms_kernel(const float* __restrict__ boxes,
                                const float* __restrict__ cls,
                                float* __restrict__ out)
{
    const int c = blockIdx.x;   // class
    const int b = blockIdx.y;   // batch
    const int t = threadIdx.x;

    __shared__ float ss[N_CELLS];
    __shared__ float sx1[N_CELLS], sy1[N_CELLS], sx2[N_CELLS], sy2[N_CELLS];
    __shared__ float sa[N_CELLS];
    __shared__ int   sorder[N_CELLS];
    __shared__ int   skeep[N_CELLS];

    if (t < N_CELLS) {
        const int row = b * N_CELLS + t;
        ss[t] = cls[row * NUM_CLS + c];
        float x1 = boxes[row * 4 + 0];
        float y1 = boxes[row * 4 + 1];
        float x2 = boxes[row * 4 + 2];
        float y2 = boxes[row * 4 + 3];
        sx1[t] = x1; sy1[t] = y1; sx2[t] = x2; sy2[t] = y2;
        sa[t] = fmaxf(x2 - x1, 0.0f) * fmaxf(y2 - y1, 0.0f);
    }
    __syncthreads();

    if (t < N_CELLS) {
        float sp = ss[t];
        int r = 0;
        for (int q = 0; q < N_CELLS; q++) {
            float sq = ss[q];
            r += (sq > sp) || (sq == sp && q < t);
        }
        sorder[r] = t;
        skeep[r]  = (sp > CONF_TH) ? 1 : 0;
    }
    __syncthreads();

    int pj = 0;
    float bx1 = 0.f, by1 = 0.f, bx2 = 0.f, by2 = 0.f, ba = 0.f;
    if (t < N_CELLS) {
        pj  = sorder[t];
        bx1 = sx1[pj]; by1 = sy1[pj]; bx2 = sx2[pj]; by2 = sy2[pj]; ba = sa[pj];
    }

    for (int i = 0; i < N_CELLS - 1; i++) {
        if (skeep[i]) {
            int pi = sorder[i];
            float ax1 = sx1[pi], ay1 = sy1[pi];
            float ax2 = sx2[pi], ay2 = sy2[pi];
            float aa  = sa[pi];
            if (t < N_CELLS && t > i && skeep[t]) {
                float ix1 = fmaxf(ax1, bx1), iy1 = fmaxf(ay1, by1);
                float ix2 = fminf(ax2, bx2), iy2 = fminf(ay2, by2);
                float inter = fmaxf(ix2 - ix1, 0.0f) * fmaxf(iy2 - iy1, 0.0f);
                float iou = inter / (aa + ba - inter + 1e-14f);
                if (iou > NMS_TH) skeep[t] = 0;
            }
        }
        __syncthreads();
    }

    if (t < N_CELLS) {
        const int row = b * N_CELLS + pj;
        out[row * 24 + 4 + c] = ss[pj] * (skeep[t] ? 1.0f : 0.0f);
    }
}

// ---------------------------------------------------------------------------
// Launch
// ---------------------------------------------------------------------------
extern "C" void kernel_launch(void* const* d_in, const int* in_sizes, int n_in,
                              void* d_out, int out_size)
{
    const float* x  = (const float*)d_in[0];
    const float* w1 = (const float*)d_in[1];
    const float* w2 = (const float*)d_in[2];
    const float* w3 = (const float*)d_in[3];
    const float* w4 = (const float*)d_in[4];
    const float* w5 = (const float*)d_in[5];
    const float* wh = (const float*)d_in[6];
    float* out = (float*)d_out;

    float *bufA, *bufB, *pred, *boxes, *cls;
    cudaGetSymbolAddress((void**)&bufA, g_bufA);
    cudaGetSymbolAddress((void**)&bufB, g_bufB);
    cudaGetSymbolAddress((void**)&pred, g_pred);
    cudaGetSymbolAddress((void**)&boxes, g_boxes);
    cudaGetSymbolAddress((void**)&cls, g_cls);

    float* h1 = bufA;
    float* h2 = bufB;
    float* h3 = bufA;
    float* h4 = bufB;
    float* h5 = bufA;

    {   // L1: 3 -> 64, 448 -> 224
        constexpr int NTX = (224 + 15) / 16, NTY = (224 + 7) / 8;
        conv3x3s2_relu<3, 64, 448, 448><<<dim3(NTX * NTY, 1, BATCH), 128>>>(x, w1, h1);
    }
    {   // L2: 64 -> 128, 224 -> 112
        constexpr int NTX = (112 + 15) / 16, NTY = (112 + 7) / 8;
        conv3x3s2_relu<64, 128, 224, 224><<<dim3(NTX * NTY, 2, BATCH), 128>>>(h1, w2, h2);
    }
    {   // L3: 128 -> 256, 112 -> 56
        constexpr int NTX = (56 + 15) / 16, NTY = (56 + 7) / 8;
        conv3x3s2_relu<128, 256, 112, 112><<<dim3(NTX * NTY, 4, BATCH), 128>>>(h2, w3, h3);
    }
    {   // L4: 256 -> 512, 56 -> 28
        constexpr int NTX = (28 + 15) / 16, NTY = (28 + 7) / 8;
        conv3x3s2_relu<256, 512, 56, 56><<<dim3(NTX * NTY, 8, BATCH), 128>>>(h3, w4, h4);
    }
    {   // L5: 512 -> 512, 28 -> 14
        constexpr int NTX = (14 + 15) / 16, NTY = (14 + 7) / 8;
        conv3x3s2_relu<512, 512, 28, 28><<<dim3(NTX * NTY, 8, BATCH), 128>>>(h4, w5, h5);
    }

    yolo_head_kernel<<<dim3(BATCH, HEAD_OUT), 224>>>(h5, wh, pred);
    yolo_decode_kernel<<<BATCH, 224>>>(pred, boxes, cls, out);
    yolo_nms_kernel<<<dim3(NUM_CLS, BATCH), 224>>>(boxes, cls, out);
}